// round 1
// baseline (speedup 1.0000x reference)
#include <cuda_runtime.h>
#include <math.h>

#define NS 16          // samples per block
#define HDIM 512
#define NTHREADS 256

struct Params {
  const float *tokens;
  const float *ent_W1, *ent_b1, *ent_W2, *ent_b2;
  const float *ent_Wpos, *ent_bpos, *ent_Wc, *ent_bc, *ent_Wv, *ent_bv;
  const float *pad_W1, *pad_b1, *pad_W2, *pad_b2;
  const float *attn_W, *attn_b;
  const float *b_Wpos, *b_bpos, *b_Wc, *b_bc, *b_Wv, *b_bv;
  const float *gs_W, *gs_b;
  float *out;
};

__device__ __forceinline__ float softplusf(float x) {
  // stable softplus, matches jax.nn.softplus to fp32 precision
  return (x > 20.f) ? x : log1pf(expf(x));
}

__global__ void __launch_bounds__(NTHREADS, 2)
spectral_kernel(Params p, int B) {
  extern __shared__ float sm[];
  float* s_tok  = sm;                     // NS*100
  float* s_h1   = s_tok + NS * 100;       // NS*HDIM
  float* s_h2   = s_h1  + NS * HDIM;      // NS*HDIM
  float* s_entH = s_h2  + NS * HDIM;      // NS*3*21
  float* s_padH = s_entH + NS * 63;       // NS*6*22

  const int t  = threadIdx.x;
  const int s0 = blockIdx.x * NS;

  // ---- load token tile ----
  for (int i = t; i < NS * 100; i += NTHREADS)
    s_tok[i] = p.tokens[(size_t)s0 * 100 + i];
  __syncthreads();

  // ---- 9 row-groups: 3 entities (own weights) + 6 pads (shared weights) ----
  for (int g = 0; g < 9; ++g) {
    const float *W1, *b1, *W2, *b2;
    int xrow = g;
    if (g < 3) {
      W1 = p.ent_W1 + g * 10 * HDIM; b1 = p.ent_b1 + g * HDIM;
      W2 = p.ent_W2 + g * HDIM * HDIM; b2 = p.ent_b2 + g * HDIM;
    } else {
      W1 = p.pad_W1; b1 = p.pad_b1; W2 = p.pad_W2; b2 = p.pad_b2;
    }

    // ===== Phase A: h1 = relu(x @ W1 + b1), x is (NS,10) =====
    #pragma unroll
    for (int j = 0; j < 2; ++j) {
      int n = t + 256 * j;
      float w[10];
      #pragma unroll
      for (int k = 0; k < 10; ++k) w[k] = W1[k * HDIM + n];
      float bb = b1[n];
      #pragma unroll
      for (int s = 0; s < NS; ++s) {
        const float* x = s_tok + s * 100 + xrow * 10;
        float acc = bb;
        #pragma unroll
        for (int k = 0; k < 10; ++k) acc = fmaf(x[k], w[k], acc);
        s_h1[s * HDIM + n] = fmaxf(acc, 0.f);
      }
    }
    __syncthreads();

    // ===== Phase B: h2 = relu(h1 @ W2 + b2), the 512x512 hot loop =====
    float acc0[NS], acc1[NS];
    #pragma unroll
    for (int s = 0; s < NS; ++s) { acc0[s] = 0.f; acc1[s] = 0.f; }

    for (int k = 0; k < HDIM; k += 4) {
      float wa[4], wb[4];
      #pragma unroll
      for (int kk = 0; kk < 4; ++kk) {
        wa[kk] = W2[(k + kk) * HDIM + t];
        wb[kk] = W2[(k + kk) * HDIM + t + 256];
      }
      #pragma unroll
      for (int s = 0; s < NS; ++s) {
        float4 av = *reinterpret_cast<const float4*>(s_h1 + s * HDIM + k);
        acc0[s] = fmaf(av.x, wa[0], acc0[s]);
        acc0[s] = fmaf(av.y, wa[1], acc0[s]);
        acc0[s] = fmaf(av.z, wa[2], acc0[s]);
        acc0[s] = fmaf(av.w, wa[3], acc0[s]);
        acc1[s] = fmaf(av.x, wb[0], acc1[s]);
        acc1[s] = fmaf(av.y, wb[1], acc1[s]);
        acc1[s] = fmaf(av.z, wb[2], acc1[s]);
        acc1[s] = fmaf(av.w, wb[3], acc1[s]);
      }
    }
    {
      float b0v = b2[t], b1v = b2[t + 256];
      #pragma unroll
      for (int s = 0; s < NS; ++s) {
        s_h2[s * HDIM + t]       = fmaxf(acc0[s] + b0v, 0.f);
        s_h2[s * HDIM + t + 256] = fmaxf(acc1[s] + b1v, 0.f);
      }
    }
    __syncthreads();

    // ===== Phase C: head projections (linear in h2) =====
    if (g < 3) {
      int e = g;
      for (int idx = t; idx < NS * 21; idx += NTHREADS) {
        int s = idx / 21, c = idx % 21;
        const float* wcol; int stride;
        if (c < 3)       { wcol = p.ent_Wpos + e * HDIM * 3 + c;        stride = 3; }
        else if (c < 12) { wcol = p.ent_Wc   + e * HDIM * 9 + (c - 3);  stride = 9; }
        else             { wcol = p.ent_Wv   + e * HDIM * 9 + (c - 12); stride = 9; }
        float acc = 0.f;
        const float* h2r = s_h2 + s * HDIM;
        #pragma unroll 8
        for (int k = 0; k < HDIM; ++k) acc = fmaf(h2r[k], wcol[k * stride], acc);
        s_entH[s * 63 + e * 21 + c] = acc;
      }
    } else {
      int pd = g - 3;
      // heads are linear, so softmax-weighted agg of hp2 == weighted agg of head outputs
      for (int idx = t; idx < NS * 22; idx += NTHREADS) {
        int s = idx / 22, c = idx % 22;
        const float* wcol; int stride;
        if (c < 3)       { wcol = p.b_Wpos + c;        stride = 3; }
        else if (c < 12) { wcol = p.b_Wc + (c - 3);    stride = 9; }
        else if (c < 21) { wcol = p.b_Wv + (c - 12);   stride = 9; }
        else             { wcol = p.attn_W;            stride = 1; }
        float acc = 0.f;
        const float* h2r = s_h2 + s * HDIM;
        #pragma unroll 8
        for (int k = 0; k < HDIM; ++k) acc = fmaf(h2r[k], wcol[k * stride], acc);
        s_padH[(s * 6 + pd) * 22 + c] = acc;
      }
    }
    __syncthreads();
  }

  // ===== Phase D: per-sample epilogue (one thread per sample) =====
  if (t < NS) {
    int s = t;
    float* o = p.out + (size_t)(s0 + s) * 105;

    // softmax over the 6 pad attention logits
    float lg[6];
    float m = -1e30f;
    float attnb = p.attn_b[0];
    #pragma unroll
    for (int pd = 0; pd < 6; ++pd) {
      lg[pd] = s_padH[(s * 6 + pd) * 22 + 21] + attnb;
      m = fmaxf(m, lg[pd]);
    }
    float den = 0.f;
    #pragma unroll
    for (int pd = 0; pd < 6; ++pd) { lg[pd] = expf(lg[pd] - m); den += lg[pd]; }
    float inv = 1.f / den;

    float agg[21];
    #pragma unroll
    for (int c = 0; c < 21; ++c) agg[c] = 0.f;
    #pragma unroll
    for (int pd = 0; pd < 6; ++pd) {
      float w = lg[pd] * inv;
      #pragma unroll
      for (int c = 0; c < 21; ++c)
        agg[c] = fmaf(w, s_padH[(s * 6 + pd) * 22 + c], agg[c]);
    }

    float pos[4][3], coef[4][9], cov[4][9];
    for (int e = 0; e < 3; ++e) {
      const float* eh = s_entH + s * 63 + e * 21;
      for (int d = 0; d < 3; ++d) pos[e][d]  = eh[d]      + p.ent_bpos[e * 3 + d];
      for (int c = 0; c < 9; ++c) coef[e][c] = eh[3 + c]  + p.ent_bc[e * 9 + c];
      for (int c = 0; c < 9; ++c) cov[e][c]  = softplusf(eh[12 + c] + p.ent_bv[e * 9 + c]);
    }
    for (int d = 0; d < 3; ++d) pos[3][d]  = agg[d]      + p.b_bpos[d];
    for (int c = 0; c < 9; ++c) coef[3][c] = agg[3 + c]  + p.b_bc[c];
    for (int c = 0; c < 9; ++c) cov[3][c]  = softplusf(agg[12 + c] + p.b_bv[c]);

    // field_flat: per entity i -> [coef(9), cov(9), wall(6)]
    for (int i = 0; i < 4; ++i) {
      float x = pos[i][0], y = pos[i][1], z = pos[i][2];
      float wf[6];
      wf[0] = (4096.f - x) / 1000.f;
      wf[1] = (4096.f + x) / 1000.f;
      wf[2] = (5120.f - y) / 1000.f;
      wf[3] = (5120.f + y) / 1000.f;
      wf[4] = (z - 0.f) / 1000.f;
      wf[5] = (2044.f - z) / 1000.f;
      for (int c = 0; c < 9; ++c) o[i * 24 + c]      = coef[i][c];
      for (int c = 0; c < 9; ++c) o[i * 24 + 9 + c]  = cov[i][c];
      for (int c = 0; c < 6; ++c) o[i * 24 + 18 + c] = wf[c];
    }

    // tri: upper triangle of I = exp(-d2/(2*sigma^2)) * (coef_i . coef_j)/tau
    const int iu[6] = {0, 0, 0, 1, 1, 2};
    const int ju[6] = {1, 2, 3, 2, 3, 3};
    for (int q = 0; q < 6; ++q) {
      int i = iu[q], j = ju[q];
      float d2 = 0.f;
      for (int d = 0; d < 3; ++d) {
        float df = pos[i][d] - pos[j][d];
        d2 = fmaf(df, df, d2);
      }
      float cd = 0.f;
      for (int c = 0; c < 9; ++c) cd = fmaf(coef[i][c], coef[j][c], cd);
      o[96 + q] = expf(-2.f * d2) * cd;   // 2*sigma^2 = 0.5 ; tau = 1
    }

    // game: tokens row 9 @ gs_W + gs_b
    for (int d = 0; d < 3; ++d) {
      float gacc = p.gs_b[d];
      for (int k = 0; k < 10; ++k)
        gacc = fmaf(s_tok[s * 100 + 90 + k], p.gs_W[k * 3 + d], gacc);
      o[102 + d] = gacc;
    }
  }
}

extern "C" void kernel_launch(void* const* d_in, const int* in_sizes, int n_in,
                              void* d_out, int out_size) {
  Params p;
  p.tokens   = (const float*)d_in[0];
  p.ent_W1   = (const float*)d_in[1];
  p.ent_b1   = (const float*)d_in[2];
  p.ent_W2   = (const float*)d_in[3];
  p.ent_b2   = (const float*)d_in[4];
  p.ent_Wpos = (const float*)d_in[5];
  p.ent_bpos = (const float*)d_in[6];
  p.ent_Wc   = (const float*)d_in[7];
  p.ent_bc   = (const float*)d_in[8];
  p.ent_Wv   = (const float*)d_in[9];
  p.ent_bv   = (const float*)d_in[10];
  p.pad_W1   = (const float*)d_in[11];
  p.pad_b1   = (const float*)d_in[12];
  p.pad_W2   = (const float*)d_in[13];
  p.pad_b2   = (const float*)d_in[14];
  p.attn_W   = (const float*)d_in[15];
  p.attn_b   = (const float*)d_in[16];
  p.b_Wpos   = (const float*)d_in[17];
  p.b_bpos   = (const float*)d_in[18];
  p.b_Wc     = (const float*)d_in[19];
  p.b_bc     = (const float*)d_in[20];
  p.b_Wv     = (const float*)d_in[21];
  p.b_bv     = (const float*)d_in[22];
  p.gs_W     = (const float*)d_in[23];
  p.gs_b     = (const float*)d_in[24];
  p.out      = (float*)d_out;

  int B = in_sizes[0] / 100;      // tokens is (B,10,10)
  int blocks = B / NS;            // B=32768 -> 2048 blocks

  size_t smem = (size_t)(NS * 100 + 2 * NS * HDIM + NS * 63 + NS * 132) * sizeof(float);
  cudaFuncSetAttribute(spectral_kernel, cudaFuncAttributeMaxDynamicSharedMemorySize,
                       (int)smem);
  spectral_kernel<<<blocks, NTHREADS, smem>>>(p, B);
}